// round 3
// baseline (speedup 1.0000x reference)
#include <cuda_runtime.h>
#include <math.h>

// ---------------------------------------------------------------------------
// Scratch accumulators (__device__ globals, zero-initialized at module load;
// the last block resets them after finalizing so graph replays stay correct).
// ---------------------------------------------------------------------------
__device__ double       g_seg   = 0.0;   // seg BCE raw sum
__device__ float        g_det   = 0.0f;  // sum of per-(scale,image) det contributions
__device__ float        g_cls   = 0.0f;  // cls focal raw sum
__device__ unsigned int g_count = 0u;    // block arrival counter

// ---------------------------------------------------------------------------
// Math helpers: one __expf + one __logf + fast div per element
// ---------------------------------------------------------------------------
__device__ __forceinline__ float bce_f(float x, float y) {
    float e = __expf(-fabsf(x));
    return fmaxf(x, 0.0f) - x * y + __logf(1.0f + e);
}

// focal element with binary target (alpha=0.25, gamma=2)
__device__ __forceinline__ float focal_el(float x, bool t1) {
    float e   = __expf(-fabsf(x));
    float l1p = __logf(1.0f + e);
    float d   = __fdividef(1.0f, 1.0f + e);
    float sig = (x >= 0.0f) ? d : e * d;          // sigmoid(x)
    if (t1) {
        float om = 1.0f - sig;
        float sp = fmaxf(-x, 0.0f) + l1p;          // bce(x,1)
        return 0.25f * om * om * sp;
    } else {
        float sp = fmaxf(x, 0.0f) + l1p;           // bce(x,0)
        return 0.75f * sig * sig * sp;
    }
}

// Block reduction; result valid on thread 0.
__device__ __forceinline__ float block_reduce(float v, float* sh) {
    int lane = threadIdx.x & 31;
    int wid  = threadIdx.x >> 5;
    #pragma unroll
    for (int o = 16; o; o >>= 1) v += __shfl_down_sync(0xffffffffu, v, o);
    if (lane == 0) sh[wid] = v;
    __syncthreads();
    int nw = (blockDim.x + 31) >> 5;
    v = (threadIdx.x < nw) ? sh[threadIdx.x] : 0.0f;
    if (wid == 0) {
        #pragma unroll
        for (int o = 16; o; o >>= 1) v += __shfl_down_sync(0xffffffffu, v, o);
    }
    __syncthreads();
    return v;
}

// ---------------------------------------------------------------------------
// Detection for one (scale, image): the whole block loops over all L locations.
// Folds (cls_l + reg_l + cen_l) / (3*B) into g_det.
// ---------------------------------------------------------------------------
template <int STRIDE, int HWDIM>
__device__ void det_image(int b,
                          const float* __restrict__ cls,
                          const float* __restrict__ reg,
                          const float* __restrict__ cent,
                          const float* __restrict__ boxes,
                          const int*   __restrict__ labels,
                          float* sh) {
    const int NB = 20;
    const int L  = HWDIM * HWDIM;

    __shared__ float sx0[NB], sy0[NB], sx1[NB], sy1[NB], sa[NB];
    __shared__ int   slab[NB];
    if (threadIdx.x < NB) {
        int j = threadIdx.x;
        const float* bp = boxes + ((long long)b * NB + j) * 4;
        float cx = bp[0] * 512.0f, cy = bp[1] * 512.0f;
        float w  = bp[2] * 512.0f, h  = bp[3] * 512.0f;
        float x0 = cx - w * 0.5f, y0 = cy - h * 0.5f;
        float x1 = cx + w * 0.5f, y1 = cy + h * 0.5f;
        sx0[j] = x0; sy0[j] = y0; sx1[j] = x1; sy1[j] = y1;
        sa[j]  = (x1 - x0) * (y1 - y0);
        slab[j] = labels[b * NB + j];
    }
    __syncthreads();

    const float inv_stride = 1.0f / (float)STRIDE;
    float cls_sum = 0.0f, reg_sum = 0.0f, cen_sum = 0.0f, npos_f = 0.0f;

    for (int l = threadIdx.x; l < L; l += blockDim.x) {
        const int hh = l / HWDIM, ww = l - hh * HWDIM;
        const float lx = (ww + 0.5f) * (float)STRIDE;
        const float ly = (hh + 0.5f) * (float)STRIDE;

        float best_a = INFINITY;
        int   best   = 0;
        bool  pos    = false;
        #pragma unroll 5
        for (int j = 0; j < NB; j++) {
            float l_ = lx - sx0[j];
            float t_ = ly - sy0[j];
            float r_ = sx1[j] - lx;
            float m_ = sy1[j] - ly;
            float mn = fminf(fminf(l_, t_), fminf(r_, m_));
            bool ins = mn > 0.0f;
            pos = pos || ins;
            float a = ins ? sa[j] : INFINITY;
            if (a < best_a) { best_a = a; best = j; }   // strict < = first-min
        }

        float rt0 = (lx - sx0[best]) * inv_stride;
        float rt1 = (ly - sy0[best]) * inv_stride;
        float rt2 = (sx1[best] - lx) * inv_stride;
        float rt3 = (sy1[best] - ly) * inv_stride;
        int label = pos ? slab[best] : -1;

        #pragma unroll
        for (int c = 0; c < 4; c++) {
            float x = cls[((long long)b * 5 + (c + 1)) * L + l];
            cls_sum += focal_el(x, c == label);
        }

        if (pos) {
            float rt[4] = {rt0, rt1, rt2, rt3};
            float sl1 = 0.0f;
            #pragma unroll
            for (int c = 0; c < 4; c++) {
                float d  = reg[((long long)b * 4 + c) * L + l] - rt[c];
                float ad = fabsf(d);
                sl1 += (ad < 1.0f) ? 0.5f * d * d : ad - 0.5f;
            }
            reg_sum += sl1 * 0.25f;

            const float eps = 1e-6f;
            float mnlr = fminf(rt0, rt2), mxlr = fmaxf(rt0, rt2);
            float mntb = fminf(rt1, rt3), mxtb = fmaxf(rt1, rt3);
            float v = __fdividef(mnlr, mxlr + eps) * __fdividef(mntb, mxtb + eps);
            v = fminf(fmaxf(v, 0.0f), 1.0f);
            cen_sum += bce_f(cent[(long long)b * L + l], sqrtf(v));
            npos_f  += 1.0f;
        }
    }

    float ct = block_reduce(cls_sum, sh);
    float rt_ = block_reduce(reg_sum, sh);
    float ce = block_reduce(cen_sum, sh);
    float np = block_reduce(npos_f,  sh);
    if (threadIdx.x == 0) {
        float cls_l = ct / (float)(L * 4);
        float reg_l = (np > 0.0f) ? rt_ / np : 0.0f;
        float cen_l = (np > 0.0f) ? ce / np : 0.0f;
        atomicAdd(&g_det, (cls_l + reg_l + cen_l) * (1.0f / 96.0f));  // /(3*B)
    }
}

// ---------------------------------------------------------------------------
// Single fused kernel, exactly one wave: 456 blocks = 152 SMs * 3.
//   [0, NSEG)            seg grid-stride (memory-bound bulk, starts first)
//   [NSEG, NSEG+32)      det scale0, b = bid-NSEG
//   [+32, +64)           det scale1
//   [+64, +96)           det scale2
//   last block           cls focal
// Last-arriving block finalizes, writes out, resets accumulators.
// ---------------------------------------------------------------------------
static const int NSEG = 359;
static const int TOTAL_BLOCKS = NSEG + 96 + 1;   // 456

__global__ void __launch_bounds__(256, 3)
main_kernel(const float* __restrict__ seg_logits,
            const int*   __restrict__ seg_mask,
            const float* __restrict__ cls_s0,
            const float* __restrict__ cls_s1,
            const float* __restrict__ cls_s2,
            const float* __restrict__ reg_s0,
            const float* __restrict__ reg_s1,
            const float* __restrict__ reg_s2,
            const float* __restrict__ cen_s0,
            const float* __restrict__ cen_s1,
            const float* __restrict__ cen_s2,
            const float* __restrict__ boxes,
            const int*   __restrict__ labels,
            const float* __restrict__ cls_pred,
            const int*   __restrict__ cls_target,
            float* __restrict__ out, int out_n) {
    __shared__ float sh[32];
    const int bid = blockIdx.x;

    if (bid < NSEG) {
        // ---- segmentation BCE: (32,4,512,512) logits vs broadcast mask ----
        const long long HW   = 512LL * 512LL;        // 2^18
        const long long NVEC = (32LL * HW) >> 2;     // float4 groups
        const long long stride = (long long)NSEG * blockDim.x;
        float acc = 0.0f;
        for (long long v = (long long)bid * blockDim.x + threadIdx.x;
             v < NVEC; v += stride) {
            long long s  = v << 2;
            long long b  = s >> 18;
            long long hw = s & (HW - 1);

            int4 m = *reinterpret_cast<const int4*>(seg_mask + b * HW + hw);
            float y0 = (float)m.x, y1 = (float)m.y, y2 = (float)m.z, y3 = (float)m.w;

            #pragma unroll
            for (int c = 0; c < 4; c++) {
                float4 x = *reinterpret_cast<const float4*>(
                    seg_logits + (b * 4 + c) * HW + hw);
                acc += bce_f(x.x, y0);
                acc += bce_f(x.y, y1);
                acc += bce_f(x.z, y2);
                acc += bce_f(x.w, y3);
            }
        }
        float bs = block_reduce(acc, sh);
        if (threadIdx.x == 0) atomicAdd(&g_seg, (double)bs);
    } else if (bid < NSEG + 32) {
        det_image<8, 64>(bid - NSEG, cls_s0, reg_s0, cen_s0, boxes, labels, sh);
    } else if (bid < NSEG + 64) {
        det_image<16, 32>(bid - NSEG - 32, cls_s1, reg_s1, cen_s1, boxes, labels, sh);
    } else if (bid < NSEG + 96) {
        det_image<32, 16>(bid - NSEG - 64, cls_s2, reg_s2, cen_s2, boxes, labels, sh);
    } else {
        // cls focal: (32,10) pred, (32,) target — 320 elements
        float v = 0.0f;
        for (int i = threadIdx.x; i < 320; i += blockDim.x) {
            int bb = i / 10, cc = i - bb * 10;
            v += focal_el(cls_pred[i], cls_target[bb] == cc);
        }
        float s = block_reduce(v, sh);
        if (threadIdx.x == 0) atomicAdd(&g_cls, s);
    }

    // ---- last-block finalize ----
    __shared__ int is_last;
    if (threadIdx.x == 0) {
        __threadfence();
        unsigned old = atomicAdd(&g_count, 1u);
        is_last = (old == (unsigned)(gridDim.x - 1)) ? 1 : 0;
    }
    __syncthreads();
    if (is_last) {
        __shared__ float res;
        if (threadIdx.x == 0) {
            double total = g_seg / (32.0 * 4.0 * 512.0 * 512.0)
                         + (double)g_det
                         + 0.5 * (double)g_cls / 320.0;
            res = (float)total;
            // reset for next graph replay
            g_seg = 0.0; g_det = 0.0f; g_cls = 0.0f; g_count = 0u;
        }
        __syncthreads();
        for (int k = threadIdx.x; k < out_n; k += blockDim.x) out[k] = res;
    }
}

// ---------------------------------------------------------------------------
// Launch: single kernel node.
// ---------------------------------------------------------------------------
extern "C" void kernel_launch(void* const* d_in, const int* in_sizes, int n_in,
                              void* d_out, int out_size) {
    main_kernel<<<TOTAL_BLOCKS, 256>>>(
        (const float*)d_in[0],  (const int*)d_in[1],
        (const float*)d_in[2],  (const float*)d_in[3],  (const float*)d_in[4],
        (const float*)d_in[5],  (const float*)d_in[6],  (const float*)d_in[7],
        (const float*)d_in[8],  (const float*)d_in[9],  (const float*)d_in[10],
        (const float*)d_in[11], (const int*)d_in[12],
        (const float*)d_in[13], (const int*)d_in[14],
        (float*)d_out, out_size);
}

// round 4
// speedup vs baseline: 1.2600x; 1.2600x over previous
#include <cuda_runtime.h>
#include <math.h>

// ---------------------------------------------------------------------------
// Scratch accumulators (__device__ globals, zero-initialized at load; the
// finalizing block resets them so every graph replay starts from zeros).
// ---------------------------------------------------------------------------
__device__ double       g_seg = 0.0;            // seg BCE raw sum
__device__ float        g_det[3][32][4];        // per scale/image: cls,reg,cen,npos
__device__ float        g_cls = 0.0f;           // cls focal raw sum
__device__ unsigned int g_count = 0u;           // block arrival counter

// ---------------------------------------------------------------------------
// Math helpers
// ---------------------------------------------------------------------------
__device__ __forceinline__ float bce_f(float x, float y) {
    float e = __expf(-fabsf(x));
    return fmaxf(x, 0.0f) - x * y + __logf(1.0f + e);
}

__device__ __forceinline__ float focal_el(float x, bool t1) {
    float e   = __expf(-fabsf(x));
    float l1p = __logf(1.0f + e);
    float d   = __fdividef(1.0f, 1.0f + e);
    float sig = (x >= 0.0f) ? d : e * d;          // sigmoid(x)
    if (t1) {
        float om = 1.0f - sig;
        float sp = fmaxf(-x, 0.0f) + l1p;          // bce(x,1)
        return 0.25f * om * om * sp;
    } else {
        float sp = fmaxf(x, 0.0f) + l1p;           // bce(x,0)
        return 0.75f * sig * sig * sp;
    }
}

// Block reduction; result valid on thread 0.
__device__ __forceinline__ float block_reduce(float v, float* sh) {
    int lane = threadIdx.x & 31;
    int wid  = threadIdx.x >> 5;
    #pragma unroll
    for (int o = 16; o; o >>= 1) v += __shfl_down_sync(0xffffffffu, v, o);
    if (lane == 0) sh[wid] = v;
    __syncthreads();
    int nw = (blockDim.x + 31) >> 5;
    v = (threadIdx.x < nw) ? sh[threadIdx.x] : 0.0f;
    if (wid == 0) {
        #pragma unroll
        for (int o = 16; o; o >>= 1) v += __shfl_down_sync(0xffffffffu, v, o);
    }
    __syncthreads();
    return v;
}

// ---------------------------------------------------------------------------
// Detection chunk: one block handles 256 locations of (scale, image b).
// blockDim.x == 256 -> each thread owns one location.
// ---------------------------------------------------------------------------
template <int STRIDE, int HWDIM, int SCALE>
__device__ void det_chunk(int b, int chunk,
                          const float* __restrict__ cls,
                          const float* __restrict__ reg,
                          const float* __restrict__ cent,
                          const float* __restrict__ boxes,
                          const int*   __restrict__ labels,
                          float* sh) {
    const int NB = 20;
    const int L  = HWDIM * HWDIM;

    __shared__ float sx0[NB], sy0[NB], sx1[NB], sy1[NB], sa[NB];
    __shared__ int   slab[NB];
    if (threadIdx.x < NB) {
        int j = threadIdx.x;
        const float* bp = boxes + ((long long)b * NB + j) * 4;
        float cx = bp[0] * 512.0f, cy = bp[1] * 512.0f;
        float w  = bp[2] * 512.0f, h  = bp[3] * 512.0f;
        float x0 = cx - w * 0.5f, y0 = cy - h * 0.5f;
        float x1 = cx + w * 0.5f, y1 = cy + h * 0.5f;
        sx0[j] = x0; sy0[j] = y0; sx1[j] = x1; sy1[j] = y1;
        sa[j]  = (x1 - x0) * (y1 - y0);
        slab[j] = labels[b * NB + j];
    }
    __syncthreads();

    const int l  = chunk * 256 + threadIdx.x;   // location index (always < L)
    const int hh = l / HWDIM, ww = l - hh * HWDIM;
    const float lx = (ww + 0.5f) * (float)STRIDE;
    const float ly = (hh + 0.5f) * (float)STRIDE;
    const float inv_stride = 1.0f / (float)STRIDE;

    float best_a = INFINITY;
    int   best   = 0;
    bool  pos    = false;
    #pragma unroll 5
    for (int j = 0; j < NB; j++) {
        float l_ = lx - sx0[j];
        float t_ = ly - sy0[j];
        float r_ = sx1[j] - lx;
        float m_ = sy1[j] - ly;
        float mn = fminf(fminf(l_, t_), fminf(r_, m_));
        bool ins = mn > 0.0f;
        pos = pos || ins;
        float a = ins ? sa[j] : INFINITY;
        if (a < best_a) { best_a = a; best = j; }   // strict < = first-min
    }

    float rt0 = (lx - sx0[best]) * inv_stride;
    float rt1 = (ly - sy0[best]) * inv_stride;
    float rt2 = (sx1[best] - lx) * inv_stride;
    float rt3 = (sy1[best] - ly) * inv_stride;
    int label = pos ? slab[best] : -1;

    float cls_sum = 0.0f;
    #pragma unroll
    for (int c = 0; c < 4; c++) {
        float x = cls[((long long)b * 5 + (c + 1)) * L + l];
        cls_sum += focal_el(x, c == label);
    }

    float reg_sum = 0.0f, cen_sum = 0.0f, npos_f = 0.0f;
    if (pos) {
        float rt[4] = {rt0, rt1, rt2, rt3};
        float sl1 = 0.0f;
        #pragma unroll
        for (int c = 0; c < 4; c++) {
            float d  = reg[((long long)b * 4 + c) * L + l] - rt[c];
            float ad = fabsf(d);
            sl1 += (ad < 1.0f) ? 0.5f * d * d : ad - 0.5f;
        }
        reg_sum = sl1 * 0.25f;

        const float eps = 1e-6f;
        float mnlr = fminf(rt0, rt2), mxlr = fmaxf(rt0, rt2);
        float mntb = fminf(rt1, rt3), mxtb = fmaxf(rt1, rt3);
        float v = __fdividef(mnlr, mxlr + eps) * __fdividef(mntb, mxtb + eps);
        v = fminf(fmaxf(v, 0.0f), 1.0f);
        cen_sum = bce_f(cent[(long long)b * L + l], sqrtf(v));
        npos_f  = 1.0f;
    }

    float ct  = block_reduce(cls_sum, sh);
    float rt_ = block_reduce(reg_sum, sh);
    float ce  = block_reduce(cen_sum, sh);
    float np  = block_reduce(npos_f,  sh);
    if (threadIdx.x == 0) {
        atomicAdd(&g_det[SCALE][b][0], ct);
        atomicAdd(&g_det[SCALE][b][1], rt_);
        atomicAdd(&g_det[SCALE][b][2], ce);
        atomicAdd(&g_det[SCALE][b][3], np);
    }
}

// ---------------------------------------------------------------------------
// Block layout (special blocks FIRST so wave 1 starts them; seg waves backfill)
//   [0, 512)        det scale0 : b = bid>>4, chunk = bid&15
//   [512, 640)      det scale1 : b = x>>2,  chunk = x&3
//   [640, 672)      det scale2 : b = x,     chunk = 0
//   672             cls focal
//   [673, 673+NSEG) seg grid-stride
// ---------------------------------------------------------------------------
static const int DET0_B = 512, DET1_B = 128, DET2_B = 32;
static const int CLS_BID = DET0_B + DET1_B + DET2_B;   // 672
static const int NSEG = 2047;
static const int TOTAL_BLOCKS = CLS_BID + 1 + NSEG;    // 2720

__global__ void __launch_bounds__(256, 4)
main_kernel(const float* __restrict__ seg_logits,
            const int*   __restrict__ seg_mask,
            const float* __restrict__ cls_s0,
            const float* __restrict__ cls_s1,
            const float* __restrict__ cls_s2,
            const float* __restrict__ reg_s0,
            const float* __restrict__ reg_s1,
            const float* __restrict__ reg_s2,
            const float* __restrict__ cen_s0,
            const float* __restrict__ cen_s1,
            const float* __restrict__ cen_s2,
            const float* __restrict__ boxes,
            const int*   __restrict__ labels,
            const float* __restrict__ cls_pred,
            const int*   __restrict__ cls_target,
            float* __restrict__ out, int out_n) {
    __shared__ float sh[32];
    const int bid = blockIdx.x;

    if (bid < DET0_B) {
        det_chunk<8, 64, 0>(bid >> 4, bid & 15, cls_s0, reg_s0, cen_s0, boxes, labels, sh);
    } else if (bid < DET0_B + DET1_B) {
        int x = bid - DET0_B;
        det_chunk<16, 32, 1>(x >> 2, x & 3, cls_s1, reg_s1, cen_s1, boxes, labels, sh);
    } else if (bid < CLS_BID) {
        int x = bid - DET0_B - DET1_B;
        det_chunk<32, 16, 2>(x, 0, cls_s2, reg_s2, cen_s2, boxes, labels, sh);
    } else if (bid == CLS_BID) {
        float v = 0.0f;
        for (int i = threadIdx.x; i < 320; i += blockDim.x) {
            int bb = i / 10, cc = i - bb * 10;
            v += focal_el(cls_pred[i], cls_target[bb] == cc);
        }
        float s = block_reduce(v, sh);
        if (threadIdx.x == 0) atomicAdd(&g_cls, s);
    } else {
        // ---- segmentation BCE: (32,4,512,512) logits vs broadcast mask ----
        const long long HW   = 512LL * 512LL;       // 2^18
        const long long NVEC = (32LL * HW) >> 2;    // float4 groups
        const long long stride = (long long)NSEG * blockDim.x;
        float acc = 0.0f;
        for (long long v = (long long)(bid - CLS_BID - 1) * blockDim.x + threadIdx.x;
             v < NVEC; v += stride) {
            long long s  = v << 2;
            long long b  = s >> 18;
            long long hw = s & (HW - 1);

            int4 m = *reinterpret_cast<const int4*>(seg_mask + b * HW + hw);
            float y0 = (float)m.x, y1 = (float)m.y, y2 = (float)m.z, y3 = (float)m.w;

            #pragma unroll
            for (int c = 0; c < 4; c++) {
                float4 x = *reinterpret_cast<const float4*>(
                    seg_logits + (b * 4 + c) * HW + hw);
                acc += bce_f(x.x, y0);
                acc += bce_f(x.y, y1);
                acc += bce_f(x.z, y2);
                acc += bce_f(x.w, y3);
            }
        }
        float bs = block_reduce(acc, sh);
        if (threadIdx.x == 0) atomicAdd(&g_seg, (double)bs);
    }

    // ---- last-block finalize + reset ----
    __shared__ int is_last;
    if (threadIdx.x == 0) {
        __threadfence();
        unsigned old = atomicAdd(&g_count, 1u);
        is_last = (old == (unsigned)(gridDim.x - 1)) ? 1 : 0;
    }
    __syncthreads();
    if (is_last) {
        const int i = threadIdx.x;
        float v = 0.0f;
        if (i < 96) {
            int s = i >> 5, b = i & 31;
            const int Ls = (s == 0) ? 4096 : (s == 1) ? 1024 : 256;
            float cs = g_det[s][b][0];
            float rs = g_det[s][b][1];
            float ce = g_det[s][b][2];
            float np = g_det[s][b][3];
            float cls_l = cs / (float)(Ls * 4);
            float reg_l = (np > 0.0f) ? rs / np : 0.0f;
            float cen_l = (np > 0.0f) ? ce / np : 0.0f;
            v = cls_l + reg_l + cen_l;
        }
        double seg_v = g_seg;
        float  cls_v = g_cls;
        __syncthreads();                  // all reads done before reset
        float det_tot = block_reduce(v, sh);

        __shared__ float res;
        if (i == 0) {
            double total = seg_v / (32.0 * 4.0 * 512.0 * 512.0)
                         + (double)det_tot / (3.0 * 32.0)
                         + 0.5 * (double)cls_v / 320.0;
            res = (float)total;
            g_seg = 0.0; g_cls = 0.0f; g_count = 0u;
        }
        // reset det partials for next replay
        for (int k = i; k < 3 * 32 * 4; k += blockDim.x)
            (&g_det[0][0][0])[k] = 0.0f;
        __syncthreads();
        for (int k = i; k < out_n; k += blockDim.x) out[k] = res;
    }
}

// ---------------------------------------------------------------------------
// Launch: single kernel node.
// ---------------------------------------------------------------------------
extern "C" void kernel_launch(void* const* d_in, const int* in_sizes, int n_in,
                              void* d_out, int out_size) {
    main_kernel<<<TOTAL_BLOCKS, 256>>>(
        (const float*)d_in[0],  (const int*)d_in[1],
        (const float*)d_in[2],  (const float*)d_in[3],  (const float*)d_in[4],
        (const float*)d_in[5],  (const float*)d_in[6],  (const float*)d_in[7],
        (const float*)d_in[8],  (const float*)d_in[9],  (const float*)d_in[10],
        (const float*)d_in[11], (const int*)d_in[12],
        (const float*)d_in[13], (const int*)d_in[14],
        (float*)d_out, out_size);
}

// round 5
// speedup vs baseline: 1.3268x; 1.0530x over previous
#include <cuda_runtime.h>
#include <math.h>

// ---------------------------------------------------------------------------
// Scratch accumulators (__device__ globals, zero-initialized at load; the
// finalizing block resets them so every graph replay starts from zeros).
// ---------------------------------------------------------------------------
__device__ double       g_seg = 0.0;            // seg BCE raw sum
__device__ float        g_det[3][32][4];        // per scale/image: cls,reg,cen,npos
__device__ float        g_cls = 0.0f;           // cls focal raw sum
__device__ unsigned int g_count = 0u;           // block arrival counter

// ---------------------------------------------------------------------------
// Math helpers
// ---------------------------------------------------------------------------

// log1p(e) for e in [0,1] via degree-6 polynomial in t = 2e-1.
// Chebyshev-derived (q = 3-2*sqrt(2)); abs error ~1.3e-6 over [0,1].
__device__ __forceinline__ float log1p_poly(float e) {
    float t = fmaf(2.0f, e, -1.0f);
    float p = -0.000272112f;
    p = fmaf(p, t,  0.000951563f);
    p = fmaf(p, t, -0.003058072f);
    p = fmaf(p, t,  0.012278902f);
    p = fmaf(p, t, -0.055561325f);
    p = fmaf(p, t,  0.333341848f);
    p = fmaf(p, t,  0.405465108f);
    return p;
}

// seg-path BCE: ONE MUFU (ex2) per element, log replaced by polynomial.
__device__ __forceinline__ float bce_poly(float x, float y) {
    float e = __expf(-fabsf(x));
    return fmaxf(x, 0.0f) - x * y + log1p_poly(e);
}

// exact-ish BCE for the small det/cent path
__device__ __forceinline__ float bce_f(float x, float y) {
    float e = __expf(-fabsf(x));
    return fmaxf(x, 0.0f) - x * y + __logf(1.0f + e);
}

__device__ __forceinline__ float focal_el(float x, bool t1) {
    float e   = __expf(-fabsf(x));
    float l1p = __logf(1.0f + e);
    float d   = __fdividef(1.0f, 1.0f + e);
    float sig = (x >= 0.0f) ? d : e * d;          // sigmoid(x)
    if (t1) {
        float om = 1.0f - sig;
        float sp = fmaxf(-x, 0.0f) + l1p;          // bce(x,1)
        return 0.25f * om * om * sp;
    } else {
        float sp = fmaxf(x, 0.0f) + l1p;           // bce(x,0)
        return 0.75f * sig * sig * sp;
    }
}

// Block reduction; result valid on thread 0.
__device__ __forceinline__ float block_reduce(float v, float* sh) {
    int lane = threadIdx.x & 31;
    int wid  = threadIdx.x >> 5;
    #pragma unroll
    for (int o = 16; o; o >>= 1) v += __shfl_down_sync(0xffffffffu, v, o);
    if (lane == 0) sh[wid] = v;
    __syncthreads();
    int nw = (blockDim.x + 31) >> 5;
    v = (threadIdx.x < nw) ? sh[threadIdx.x] : 0.0f;
    if (wid == 0) {
        #pragma unroll
        for (int o = 16; o; o >>= 1) v += __shfl_down_sync(0xffffffffu, v, o);
    }
    __syncthreads();
    return v;
}

// ---------------------------------------------------------------------------
// Detection chunk: one block handles 256 locations of (scale, image b).
// ---------------------------------------------------------------------------
template <int STRIDE, int HWDIM, int SCALE>
__device__ void det_chunk(int b, int chunk,
                          const float* __restrict__ cls,
                          const float* __restrict__ reg,
                          const float* __restrict__ cent,
                          const float* __restrict__ boxes,
                          const int*   __restrict__ labels,
                          float* sh) {
    const int NB = 20;
    const int L  = HWDIM * HWDIM;

    __shared__ float sx0[NB], sy0[NB], sx1[NB], sy1[NB], sa[NB];
    __shared__ int   slab[NB];
    if (threadIdx.x < NB) {
        int j = threadIdx.x;
        const float* bp = boxes + ((long long)b * NB + j) * 4;
        float cx = bp[0] * 512.0f, cy = bp[1] * 512.0f;
        float w  = bp[2] * 512.0f, h  = bp[3] * 512.0f;
        float x0 = cx - w * 0.5f, y0 = cy - h * 0.5f;
        float x1 = cx + w * 0.5f, y1 = cy + h * 0.5f;
        sx0[j] = x0; sy0[j] = y0; sx1[j] = x1; sy1[j] = y1;
        sa[j]  = (x1 - x0) * (y1 - y0);
        slab[j] = labels[b * NB + j];
    }
    __syncthreads();

    const int l  = chunk * 256 + threadIdx.x;   // location index (always < L)
    const int hh = l / HWDIM, ww = l - hh * HWDIM;
    const float lx = (ww + 0.5f) * (float)STRIDE;
    const float ly = (hh + 0.5f) * (float)STRIDE;
    const float inv_stride = 1.0f / (float)STRIDE;

    float best_a = INFINITY;
    int   best   = 0;
    bool  pos    = false;
    #pragma unroll 5
    for (int j = 0; j < NB; j++) {
        float l_ = lx - sx0[j];
        float t_ = ly - sy0[j];
        float r_ = sx1[j] - lx;
        float m_ = sy1[j] - ly;
        float mn = fminf(fminf(l_, t_), fminf(r_, m_));
        bool ins = mn > 0.0f;
        pos = pos || ins;
        float a = ins ? sa[j] : INFINITY;
        if (a < best_a) { best_a = a; best = j; }   // strict < = first-min
    }

    float rt0 = (lx - sx0[best]) * inv_stride;
    float rt1 = (ly - sy0[best]) * inv_stride;
    float rt2 = (sx1[best] - lx) * inv_stride;
    float rt3 = (sy1[best] - ly) * inv_stride;
    int label = pos ? slab[best] : -1;

    float cls_sum = 0.0f;
    #pragma unroll
    for (int c = 0; c < 4; c++) {
        float x = cls[((long long)b * 5 + (c + 1)) * L + l];
        cls_sum += focal_el(x, c == label);
    }

    float reg_sum = 0.0f, cen_sum = 0.0f, npos_f = 0.0f;
    if (pos) {
        float rt[4] = {rt0, rt1, rt2, rt3};
        float sl1 = 0.0f;
        #pragma unroll
        for (int c = 0; c < 4; c++) {
            float d  = reg[((long long)b * 4 + c) * L + l] - rt[c];
            float ad = fabsf(d);
            sl1 += (ad < 1.0f) ? 0.5f * d * d : ad - 0.5f;
        }
        reg_sum = sl1 * 0.25f;

        const float eps = 1e-6f;
        float mnlr = fminf(rt0, rt2), mxlr = fmaxf(rt0, rt2);
        float mntb = fminf(rt1, rt3), mxtb = fmaxf(rt1, rt3);
        float v = __fdividef(mnlr, mxlr + eps) * __fdividef(mntb, mxtb + eps);
        v = fminf(fmaxf(v, 0.0f), 1.0f);
        cen_sum = bce_f(cent[(long long)b * L + l], sqrtf(v));
        npos_f  = 1.0f;
    }

    float ct  = block_reduce(cls_sum, sh);
    float rt_ = block_reduce(reg_sum, sh);
    float ce  = block_reduce(cen_sum, sh);
    float np  = block_reduce(npos_f,  sh);
    if (threadIdx.x == 0) {
        atomicAdd(&g_det[SCALE][b][0], ct);
        atomicAdd(&g_det[SCALE][b][1], rt_);
        atomicAdd(&g_det[SCALE][b][2], ce);
        atomicAdd(&g_det[SCALE][b][3], np);
    }
}

// ---------------------------------------------------------------------------
// Block layout (special blocks FIRST; seg waves backfill behind them)
// ---------------------------------------------------------------------------
static const int DET0_B = 512, DET1_B = 128, DET2_B = 32;
static const int CLS_BID = DET0_B + DET1_B + DET2_B;   // 672
static const int NSEG = 2047;
static const int TOTAL_BLOCKS = CLS_BID + 1 + NSEG;    // 2720

__global__ void __launch_bounds__(256, 4)
main_kernel(const float* __restrict__ seg_logits,
            const int*   __restrict__ seg_mask,
            const float* __restrict__ cls_s0,
            const float* __restrict__ cls_s1,
            const float* __restrict__ cls_s2,
            const float* __restrict__ reg_s0,
            const float* __restrict__ reg_s1,
            const float* __restrict__ reg_s2,
            const float* __restrict__ cen_s0,
            const float* __restrict__ cen_s1,
            const float* __restrict__ cen_s2,
            const float* __restrict__ boxes,
            const int*   __restrict__ labels,
            const float* __restrict__ cls_pred,
            const int*   __restrict__ cls_target,
            float* __restrict__ out, int out_n) {
    __shared__ float sh[32];
    const int bid = blockIdx.x;

    if (bid < DET0_B) {
        det_chunk<8, 64, 0>(bid >> 4, bid & 15, cls_s0, reg_s0, cen_s0, boxes, labels, sh);
    } else if (bid < DET0_B + DET1_B) {
        int x = bid - DET0_B;
        det_chunk<16, 32, 1>(x >> 2, x & 3, cls_s1, reg_s1, cen_s1, boxes, labels, sh);
    } else if (bid < CLS_BID) {
        int x = bid - DET0_B - DET1_B;
        det_chunk<32, 16, 2>(x, 0, cls_s2, reg_s2, cen_s2, boxes, labels, sh);
    } else if (bid == CLS_BID) {
        float v = 0.0f;
        for (int i = threadIdx.x; i < 320; i += blockDim.x) {
            int bb = i / 10, cc = i - bb * 10;
            v += focal_el(cls_pred[i], cls_target[bb] == cc);
        }
        float s = block_reduce(v, sh);
        if (threadIdx.x == 0) atomicAdd(&g_cls, s);
    } else {
        // ---- segmentation BCE: (32,4,512,512) logits vs broadcast mask ----
        // 32-bit index math: all element offsets < 2^27, fits easily.
        const unsigned HW   = 512u * 512u;          // 2^18
        const unsigned NVEC = (32u * HW) >> 2;      // float4 groups: 2^23
        const unsigned stride = (unsigned)NSEG * 256u;
        float acc = 0.0f;
        for (unsigned v = (unsigned)(bid - CLS_BID - 1) * 256u + threadIdx.x;
             v < NVEC; v += stride) {
            unsigned s  = v << 2;
            unsigned b  = s >> 18;
            unsigned hw = s & (HW - 1u);

            int4 m = *reinterpret_cast<const int4*>(seg_mask + b * HW + hw);
            float y0 = (float)m.x, y1 = (float)m.y, y2 = (float)m.z, y3 = (float)m.w;

            unsigned base = (b * 4u) * HW + hw;
            #pragma unroll
            for (int c = 0; c < 4; c++) {
                float4 x = *reinterpret_cast<const float4*>(seg_logits + base + (unsigned)c * HW);
                acc += bce_poly(x.x, y0);
                acc += bce_poly(x.y, y1);
                acc += bce_poly(x.z, y2);
                acc += bce_poly(x.w, y3);
            }
        }
        float bs = block_reduce(acc, sh);
        if (threadIdx.x == 0) atomicAdd(&g_seg, (double)bs);
    }

    // ---- last-block finalize + reset ----
    __shared__ int is_last;
    if (threadIdx.x == 0) {
        __threadfence();
        unsigned old = atomicAdd(&g_count, 1u);
        is_last = (old == (unsigned)(gridDim.x - 1)) ? 1 : 0;
    }
    __syncthreads();
    if (is_last) {
        const int i = threadIdx.x;
        float v = 0.0f;
        if (i < 96) {
            int s = i >> 5, b = i & 31;
            const int Ls = (s == 0) ? 4096 : (s == 1) ? 1024 : 256;
            float cs = g_det[s][b][0];
            float rs = g_det[s][b][1];
            float ce = g_det[s][b][2];
            float np = g_det[s][b][3];
            float cls_l = cs / (float)(Ls * 4);
            float reg_l = (np > 0.0f) ? rs / np : 0.0f;
            float cen_l = (np > 0.0f) ? ce / np : 0.0f;
            v = cls_l + reg_l + cen_l;
        }
        double seg_v = g_seg;
        float  cls_v = g_cls;
        __syncthreads();                  // all reads done before reset
        float det_tot = block_reduce(v, sh);

        __shared__ float res;
        if (i == 0) {
            double total = seg_v / (32.0 * 4.0 * 512.0 * 512.0)
                         + (double)det_tot / (3.0 * 32.0)
                         + 0.5 * (double)cls_v / 320.0;
            res = (float)total;
            g_seg = 0.0; g_cls = 0.0f; g_count = 0u;
        }
        for (int k = i; k < 3 * 32 * 4; k += blockDim.x)
            (&g_det[0][0][0])[k] = 0.0f;
        __syncthreads();
        for (int k = i; k < out_n; k += blockDim.x) out[k] = res;
    }
}

// ---------------------------------------------------------------------------
// Launch: single kernel node.
// ---------------------------------------------------------------------------
extern "C" void kernel_launch(void* const* d_in, const int* in_sizes, int n_in,
                              void* d_out, int out_size) {
    main_kernel<<<TOTAL_BLOCKS, 256>>>(
        (const float*)d_in[0],  (const int*)d_in[1],
        (const float*)d_in[2],  (const float*)d_in[3],  (const float*)d_in[4],
        (const float*)d_in[5],  (const float*)d_in[6],  (const float*)d_in[7],
        (const float*)d_in[8],  (const float*)d_in[9],  (const float*)d_in[10],
        (const float*)d_in[11], (const int*)d_in[12],
        (const float*)d_in[13], (const int*)d_in[14],
        (float*)d_out, out_size);
}